// round 13
// baseline (speedup 1.0000x reference)
#include <cuda_runtime.h>
#include <cuda_bf16.h>
#include <cstdint>

#define BB  2
#define LL  1024
#define DD  256
#define UU  32
#define QPB 8
#define KC  64
#define KCH 64       // k-chunk for pv gemm
#define PITCH 72     // smem row pitch in bf16 (144B: conflict-free ldmatrix)

// ---- device scratch (no allocs allowed) ----
__device__ __align__(16) float g_q[BB*LL*UU];
__device__ __align__(16) float g_t[BB*LL*UU];
__device__ __align__(16) __nv_bfloat16 g_ph[BB*LL*LL];   // P hi (normalized)
__device__ __align__(16) __nv_bfloat16 g_pl[BB*LL*LL];   // P lo
__device__ __align__(16) __nv_bfloat16 g_vh[BB*LL*DD];   // V hi  [b][k][d]
__device__ __align__(16) __nv_bfloat16 g_vl[BB*LL*DD];   // V lo
__device__ __align__(16) __nv_bfloat16 g_wbh[DD*64];     // W stacked [k][n] hi
__device__ __align__(16) __nv_bfloat16 g_wbl[DD*64];     // W stacked lo

__device__ __forceinline__ float htanh(float x) {
    float y; asm("tanh.approx.f32 %0, %1;" : "=f"(y) : "f"(x)); return y;
}
__device__ __forceinline__ uint32_t smem_u32(const void* p) {
    uint32_t a;
    asm("{ .reg .u64 t; cvta.to.shared.u64 t, %1; cvt.u32.u64 %0, t; }" : "=r"(a) : "l"(p));
    return a;
}
__device__ __forceinline__ void ldsm4(uint32_t* r, uint32_t addr) {
    asm volatile("ldmatrix.sync.aligned.m8n8.x4.shared.b16 {%0,%1,%2,%3}, [%4];"
        : "=r"(r[0]), "=r"(r[1]), "=r"(r[2]), "=r"(r[3]) : "r"(addr));
}
__device__ __forceinline__ void ldsm2t(uint32_t* r, uint32_t addr) {
    asm volatile("ldmatrix.sync.aligned.m8n8.x2.trans.shared.b16 {%0,%1}, [%2];"
        : "=r"(r[0]), "=r"(r[1]) : "r"(addr));
}
__device__ __forceinline__ void mma16816(float* c, const uint32_t* a, const uint32_t* b) {
    asm volatile("mma.sync.aligned.m16n8k16.row.col.f32.bf16.bf16.f32 "
        "{%0,%1,%2,%3}, {%4,%5,%6,%7}, {%8,%9}, {%0,%1,%2,%3};"
        : "+f"(c[0]), "+f"(c[1]), "+f"(c[2]), "+f"(c[3])
        : "r"(a[0]), "r"(a[1]), "r"(a[2]), "r"(a[3]), "r"(b[0]), "r"(b[1]));
}
__device__ __forceinline__ void split_bf16(float v, __nv_bfloat16& h, __nv_bfloat16& l) {
    h = __float2bfloat16(v);
    l = __float2bfloat16(v - __bfloat162float(h));
}
__device__ __forceinline__ void cpasync16(uint32_t saddr, const void* gptr) {
    asm volatile("cp.async.cg.shared.global [%0], [%1], 16;" :: "r"(saddr), "l"(gptr));
}
__device__ __forceinline__ void cpasync_commit() {
    asm volatile("cp.async.commit_group;");
}
__device__ __forceinline__ void cpasync_wait0() {
    asm volatile("cp.async.wait_group 0;");
}
__device__ __forceinline__ void cpasync_wait1() {
    asm volatile("cp.async.wait_group 1;");
}

// ===========================================================================
// Kernel W: one-time split of [Wt | Wx^T] into bf16 hi/lo, [k][64] layout.
// ===========================================================================
__global__ __launch_bounds__(256) void wsplit_kernel(
    const float* __restrict__ Wt, const float* __restrict__ Wx)
{
    const int base = blockIdx.x * 1024;
    for (int i = 0; i < 4; i++) {
        const int idx = base + i * 256 + threadIdx.x;
        const int k = idx >> 6, n = idx & 63;
        const float v = (n < UU) ? Wt[k * UU + n] : Wx[(n - UU) * DD + k];
        __nv_bfloat16 h, l;
        split_bf16(v, h, l);
        g_wbh[idx] = h;
        g_wbl[idx] = l;
    }
}

// ===========================================================================
// Kernel A (MMA): [q | t] = X @ [Wt | Wx^T], split-bf16 HMMA, M-tile 16.
// ===========================================================================
#define APITCH 264
#define PA_H 0
#define PA_L (16*APITCH)
#define PB_H (2*16*APITCH)
#define PB_L (PB_H + 256*PITCH)
#define PROJ_SMEM ((PB_L + 256*PITCH) * 2)

__global__ __launch_bounds__(256) void proj_mma_kernel(
    const float* __restrict__ inputs, const float* __restrict__ bh)
{
    extern __shared__ __align__(16) __nv_bfloat16 sm[];
    const int tid  = threadIdx.x;
    const int wid  = tid >> 5;
    const int lane = tid & 31;
    const int row0 = blockIdx.x * 16;
    const uint32_t smb = smem_u32(sm);

    for (int idx = tid; idx < 16 * 64; idx += 256) {
        const int r  = idx >> 6;
        const int c4 = idx & 63;
        const float4 x = *(const float4*)(inputs + (size_t)(row0 + r) * DD + c4 * 4);
        __nv_bfloat16 h[4], l[4];
        split_bf16(x.x, h[0], l[0]); split_bf16(x.y, h[1], l[1]);
        split_bf16(x.z, h[2], l[2]); split_bf16(x.w, h[3], l[3]);
        *(uint2*)(sm + PA_H + r * APITCH + c4 * 4) = *(const uint2*)h;
        *(uint2*)(sm + PA_L + r * APITCH + c4 * 4) = *(const uint2*)l;
        *(uint2*)(g_vh + (size_t)(row0 + r) * DD + c4 * 4) = *(const uint2*)h;
        *(uint2*)(g_vl + (size_t)(row0 + r) * DD + c4 * 4) = *(const uint2*)l;
    }
    for (int idx = tid; idx < 256 * 8 * 2; idx += 256) {
        const int plane = idx >> 11;
        const int k  = (idx >> 3) & 255;
        const int n8 = (idx & 7) * 8;
        const __nv_bfloat16* src = plane ? g_wbl : g_wbh;
        const uint4 v = *(const uint4*)(src + k * 64 + n8);
        *(uint4*)(sm + (plane ? PB_L : PB_H) + k * PITCH + n8) = v;
    }
    __syncthreads();

    float acc[4] = {0.f, 0.f, 0.f, 0.f};
    #pragma unroll
    for (int kk = 0; kk < 256; kk += 16) {
        uint32_t ah[4], al[4], bhf[2], blf[2];
        {
            const int r = lane & 15;
            const int c = kk + (lane >> 4) * 8;
            ldsm4(ah, smb + (uint32_t)(PA_H + r * APITCH + c) * 2);
            ldsm4(al, smb + (uint32_t)(PA_L + r * APITCH + c) * 2);
        }
        {
            const int kr = kk + (lane & 15);
            const int c  = wid * 8;
            ldsm2t(bhf, smb + (uint32_t)(PB_H + kr * PITCH + c) * 2);
            ldsm2t(blf, smb + (uint32_t)(PB_L + kr * PITCH + c) * 2);
        }
        mma16816(acc, ah, bhf);
        mma16816(acc, ah, blf);
        mma16816(acc, al, bhf);
    }

    #pragma unroll
    for (int half = 0; half < 2; half++) {
        const int r = row0 + (lane >> 2) + half * 8;
        const int c = wid * 8 + (lane & 3) * 2;
        const float v0 = acc[half * 2 + 0];
        const float v1 = acc[half * 2 + 1];
        if (c < UU) {
            g_q[r * UU + c]     = v0;
            g_q[r * UU + c + 1] = v1;
        } else {
            g_t[r * UU + c - 32] = v0 + __ldg(bh + c - 32);
            g_t[r * UU + c - 31] = v1 + __ldg(bh + c - 31);
        }
    }
}

// ===========================================================================
// Kernel B: alpha in REGISTERS (32/lane), softmax via shfl, store P hi/lo.
// ===========================================================================
__global__ __launch_bounds__(256) void alpha_kernel(
    const float* __restrict__ Wa, const float* __restrict__ ba)
{
    __shared__ float s_t[KC][UU + 4];
    __shared__ float s_q[QPB][UU];
    __shared__ float s_wa[UU];

    const int b    = blockIdx.x / (LL / QPB);
    const int q0   = (blockIdx.x % (LL / QPB)) * QPB;
    const int tid  = threadIdx.x;
    const int warp = tid >> 5;
    const int lane = tid & 31;

    s_q[warp][lane] = g_q[((size_t)b * LL + q0 + warp) * UU + lane];
    if (tid < UU) s_wa[tid] = Wa[tid];
    const float bav = ba[0];
    __syncthreads();

    float areg[32];
    const float4* q4  = (const float4*)&s_q[warp][0];
    const float4* wa4 = (const float4*)&s_wa[0];

    #pragma unroll
    for (int c = 0; c < LL / KC; c++) {
        const float4* gt4 = (const float4*)(g_t + ((size_t)b * LL + c * KC) * UU);
        for (int i = tid; i < KC * 8; i += 256)
            ((float4*)&s_t[i >> 3][0])[i & 7] = gt4[i];
        __syncthreads();
        #pragma unroll
        for (int j = 0; j < KC / 32; j++) {
            const int kl = j * 32 + lane;
            const float4* t4 = (const float4*)&s_t[kl][0];
            float a0 = 0.f, a1 = 0.f, a2 = 0.f, a3 = 0.f;
            #pragma unroll
            for (int u4 = 0; u4 < 8; u4++) {
                const float4 qv = q4[u4];
                const float4 tv = t4[u4];
                const float4 wv = wa4[u4];
                a0 = fmaf(htanh(qv.x + tv.x), wv.x, a0);
                a1 = fmaf(htanh(qv.y + tv.y), wv.y, a1);
                a2 = fmaf(htanh(qv.z + tv.z), wv.z, a2);
                a3 = fmaf(htanh(qv.w + tv.w), wv.w, a3);
            }
            areg[c * 2 + j] = bav + ((a0 + a1) + (a2 + a3));
        }
        __syncthreads();
    }

    float lmax = areg[0];
    #pragma unroll
    for (int i = 1; i < 32; i++) lmax = fmaxf(lmax, areg[i]);
    #pragma unroll
    for (int off = 16; off; off >>= 1)
        lmax = fmaxf(lmax, __shfl_xor_sync(0xffffffffu, lmax, off));

    float lsum = 0.0f;
    #pragma unroll
    for (int i = 0; i < 32; i++) {
        areg[i] = __expf(areg[i] - lmax);
        lsum += areg[i];
    }
    #pragma unroll
    for (int off = 16; off; off >>= 1)
        lsum += __shfl_xor_sync(0xffffffffu, lsum, off);
    const float inv = 1.0f / lsum;

    const size_t rowb = ((size_t)b * LL + q0 + warp) * LL;
    #pragma unroll
    for (int i = 0; i < 32; i++) {
        const float p = areg[i] * inv;
        const __nv_bfloat16 hi = __float2bfloat16(p);
        const __nv_bfloat16 lo = __float2bfloat16(p - __bfloat162float(hi));
        g_ph[rowb + i * 32 + lane] = hi;
        g_pl[rowb + i * 32 + lane] = lo;
    }
}

// ===========================================================================
// Kernel C: warp-MMA GEMM  C[32 q x 64 d] = P @ V (split bf16, fp32 acc).
// 3-stage cp.async pipeline (wait_group 1): two chunks always in flight.
// Stage layout (bf16 units): [AH 32xP][AL 32xP][BH 64xP][BL 64xP]
// ===========================================================================
#define S_AH 0
#define S_AL (32*PITCH)
#define S_BH (2*32*PITCH)
#define S_BL (S_BH + 64*PITCH)
#define STAGE_ELE (S_BL + 64*PITCH)          // 13824 bf16 per stage
#define NSTAGE 3
#define PV_SMEM_BYTES (NSTAGE*STAGE_ELE*2)   // 82944 B

__global__ __launch_bounds__(256) void pv_kernel(float* __restrict__ out)
{
    extern __shared__ __align__(16) __nv_bfloat16 sm[];
    const int tid    = threadIdx.x;
    const int wid    = tid >> 5;
    const int lane   = tid & 31;
    const int warp_m = wid >> 2;       // 0..1 (16 rows each)
    const int warp_n = wid & 3;        // 0..3 (16 cols each)
    const int q0g    = blockIdx.x * 32;
    const int b      = q0g >> 10;
    const int n0     = blockIdx.y * 64;
    const uint32_t smb = smem_u32(sm);

    // per-thread staging slots: 6 x 16B per stage (A: 512 vecs, B: 1024 vecs)
    int s_kind[6];
    const __nv_bfloat16* s_src[6];
    int s_r[6], s_o8[6];
    uint32_t s_soff[6];
    #pragma unroll
    for (int it = 0; it < 6; it++) {
        const int i = tid + it * 256;
        if (i < 512) {
            const int plane = i >> 8;
            s_kind[it] = 0;
            s_src[it]  = plane ? g_pl : g_ph;
            s_r[it]    = (i >> 3) & 31;
            s_o8[it]   = (i & 7) * 8;
            s_soff[it] = (plane ? S_AL : S_AH) + s_r[it] * PITCH + s_o8[it];
        } else {
            const int j = i - 512;
            const int plane = j >> 9;
            s_kind[it] = 1;
            s_src[it]  = plane ? g_vl : g_vh;
            s_r[it]    = (j >> 3) & 63;
            s_o8[it]   = (j & 7) * 8;
            s_soff[it] = (plane ? S_BL : S_BH) + s_r[it] * PITCH + s_o8[it];
        }
    }

    auto issue_stage = [&](int kc0, int st) {
        const uint32_t sb = smb + (uint32_t)(st * STAGE_ELE) * 2;
        #pragma unroll
        for (int it = 0; it < 6; it++) {
            const void* g = (s_kind[it] == 0)
                ? (const void*)(s_src[it] + (size_t)(q0g + s_r[it]) * LL + kc0 + s_o8[it])
                : (const void*)(s_src[it] + (size_t)(b * LL + kc0 + s_r[it]) * DD + n0 + s_o8[it]);
            cpasync16(sb + s_soff[it] * 2, g);
        }
        cpasync_commit();
    };

    float acc[2][4];
    #pragma unroll
    for (int nt = 0; nt < 2; nt++)
        acc[nt][0] = acc[nt][1] = acc[nt][2] = acc[nt][3] = 0.f;

    issue_stage(0, 0);
    issue_stage(KCH, 1);

    #pragma unroll 1
    for (int c = 0; c < LL / KCH; c++) {
        // ensure stage c resident; keep stage c+1 in flight
        if (c < LL / KCH - 1) cpasync_wait1(); else cpasync_wait0();
        __syncthreads();   // also protects buffer (c+2)%3 from early overwrite

        if (c + 2 < LL / KCH)
            issue_stage((c + 2) * KCH, (c + 2) % NSTAGE);

        const uint32_t st = smb + (uint32_t)((c % NSTAGE) * STAGE_ELE) * 2;
        #pragma unroll
        for (int kk = 0; kk < KCH; kk += 16) {
            uint32_t ah[4], al[4], bh[2][2], bl[2][2];
            {
                const int r = warp_m * 16 + (lane & 15);
                const int col = kk + (lane >> 4) * 8;
                ldsm4(ah, st + (uint32_t)(S_AH + r * PITCH + col) * 2);
                ldsm4(al, st + (uint32_t)(S_AL + r * PITCH + col) * 2);
            }
            #pragma unroll
            for (int nt = 0; nt < 2; nt++) {
                const int kr  = kk + (lane & 15);
                const int col = warp_n * 16 + nt * 8;
                ldsm2t(bh[nt], st + (uint32_t)(S_BH + kr * PITCH + col) * 2);
                ldsm2t(bl[nt], st + (uint32_t)(S_BL + kr * PITCH + col) * 2);
            }
            #pragma unroll
            for (int nt = 0; nt < 2; nt++) {
                mma16816(acc[nt], ah, bh[nt]);
                mma16816(acc[nt], ah, bl[nt]);
                mma16816(acc[nt], al, bh[nt]);
            }
        }
    }

    #pragma unroll
    for (int nt = 0; nt < 2; nt++) {
        const int row = q0g + warp_m * 16 + (lane >> 2);
        const int col = n0 + warp_n * 16 + nt * 8 + (lane & 3) * 2;
        float* o = out + (size_t)row * DD + col;
        o[0] = acc[nt][0];
        o[1] = acc[nt][1];
        o[8 * DD + 0] = acc[nt][2];
        o[8 * DD + 1] = acc[nt][3];
    }
}

// ===========================================================================
extern "C" void kernel_launch(void* const* d_in, const int* in_sizes, int n_in,
                              void* d_out, int out_size) {
    const float* inputs = (const float*)d_in[0];
    const float* Wt     = (const float*)d_in[1];
    const float* Wx     = (const float*)d_in[2];
    const float* bh     = (const float*)d_in[3];
    const float* Wa     = (const float*)d_in[4];
    const float* ba     = (const float*)d_in[5];
    float* out = (float*)d_out;

    cudaFuncSetAttribute(proj_mma_kernel, cudaFuncAttributeMaxDynamicSharedMemorySize, PROJ_SMEM);
    cudaFuncSetAttribute(pv_kernel, cudaFuncAttributeMaxDynamicSharedMemorySize, PV_SMEM_BYTES);
    cudaFuncSetAttribute(pv_kernel, cudaFuncAttributePreferredSharedMemoryCarveout, 100);

    wsplit_kernel<<<16, 256>>>(Wt, Wx);
    proj_mma_kernel<<<BB * LL / 16, 256, PROJ_SMEM>>>(inputs, bh);
    alpha_kernel<<<BB * LL / QPB, 256>>>(Wa, ba);
    pv_kernel<<<dim3(BB * LL / 32, DD / 64), 256, PV_SMEM_BYTES>>>(out);
}

// round 14
// speedup vs baseline: 1.0382x; 1.0382x over previous
#include <cuda_runtime.h>
#include <cuda_bf16.h>
#include <cstdint>

#define BB  2
#define LL  1024
#define DD  256
#define UU  32
#define QPB 8
#define KC  64
#define KCH 64       // k-chunk for pv gemm
#define PITCH 72     // smem row pitch in bf16 (144B: conflict-free ldmatrix)

// ---- device scratch (no allocs allowed) ----
__device__ __align__(16) float g_q[BB*LL*UU];
__device__ __align__(16) float g_t[BB*LL*UU];
__device__ __align__(16) __nv_bfloat16 g_ph[BB*LL*LL];   // P hi (normalized)
__device__ __align__(16) __nv_bfloat16 g_pl[BB*LL*LL];   // P lo
__device__ __align__(16) __nv_bfloat16 g_vh[BB*LL*DD];   // V hi  [b][k][d]
__device__ __align__(16) __nv_bfloat16 g_vl[BB*LL*DD];   // V lo
__device__ __align__(16) __nv_bfloat16 g_wbh[DD*64];     // W stacked [k][n] hi
__device__ __align__(16) __nv_bfloat16 g_wbl[DD*64];     // W stacked lo

__device__ __forceinline__ float htanh(float x) {
    float y; asm("tanh.approx.f32 %0, %1;" : "=f"(y) : "f"(x)); return y;
}
__device__ __forceinline__ uint32_t smem_u32(const void* p) {
    uint32_t a;
    asm("{ .reg .u64 t; cvta.to.shared.u64 t, %1; cvt.u32.u64 %0, t; }" : "=r"(a) : "l"(p));
    return a;
}
__device__ __forceinline__ void ldsm4(uint32_t* r, uint32_t addr) {
    asm volatile("ldmatrix.sync.aligned.m8n8.x4.shared.b16 {%0,%1,%2,%3}, [%4];"
        : "=r"(r[0]), "=r"(r[1]), "=r"(r[2]), "=r"(r[3]) : "r"(addr));
}
__device__ __forceinline__ void ldsm2t(uint32_t* r, uint32_t addr) {
    asm volatile("ldmatrix.sync.aligned.m8n8.x2.trans.shared.b16 {%0,%1}, [%2];"
        : "=r"(r[0]), "=r"(r[1]) : "r"(addr));
}
__device__ __forceinline__ void mma16816(float* c, const uint32_t* a, const uint32_t* b) {
    asm volatile("mma.sync.aligned.m16n8k16.row.col.f32.bf16.bf16.f32 "
        "{%0,%1,%2,%3}, {%4,%5,%6,%7}, {%8,%9}, {%0,%1,%2,%3};"
        : "+f"(c[0]), "+f"(c[1]), "+f"(c[2]), "+f"(c[3])
        : "r"(a[0]), "r"(a[1]), "r"(a[2]), "r"(a[3]), "r"(b[0]), "r"(b[1]));
}
__device__ __forceinline__ void split_bf16(float v, __nv_bfloat16& h, __nv_bfloat16& l) {
    h = __float2bfloat16(v);
    l = __float2bfloat16(v - __bfloat162float(h));
}
__device__ __forceinline__ void cpasync16(uint32_t saddr, const void* gptr) {
    asm volatile("cp.async.cg.shared.global [%0], [%1], 16;" :: "r"(saddr), "l"(gptr));
}
__device__ __forceinline__ void cpasync_commit() {
    asm volatile("cp.async.commit_group;");
}
__device__ __forceinline__ void cpasync_wait0() {
    asm volatile("cp.async.wait_group 0;");
}
__device__ __forceinline__ void cpasync_wait1() {
    asm volatile("cp.async.wait_group 1;");
}

// ===========================================================================
// Kernel W: one-time split of [Wt | Wx^T] into bf16 hi/lo, [k][64] layout.
// ===========================================================================
__global__ __launch_bounds__(256) void wsplit_kernel(
    const float* __restrict__ Wt, const float* __restrict__ Wx)
{
    const int base = blockIdx.x * 1024;
    for (int i = 0; i < 4; i++) {
        const int idx = base + i * 256 + threadIdx.x;
        const int k = idx >> 6, n = idx & 63;
        const float v = (n < UU) ? Wt[k * UU + n] : Wx[(n - UU) * DD + k];
        __nv_bfloat16 h, l;
        split_bf16(v, h, l);
        g_wbh[idx] = h;
        g_wbl[idx] = l;
    }
}

// ===========================================================================
// Kernel A (MMA): [q | t] = X @ [Wt | Wx^T], split-bf16 HMMA, M-tile 16.
// ===========================================================================
#define APITCH 264
#define PA_H 0
#define PA_L (16*APITCH)
#define PB_H (2*16*APITCH)
#define PB_L (PB_H + 256*PITCH)
#define PROJ_SMEM ((PB_L + 256*PITCH) * 2)

__global__ __launch_bounds__(256) void proj_mma_kernel(
    const float* __restrict__ inputs, const float* __restrict__ bh)
{
    extern __shared__ __align__(16) __nv_bfloat16 sm[];
    const int tid  = threadIdx.x;
    const int wid  = tid >> 5;
    const int lane = tid & 31;
    const int row0 = blockIdx.x * 16;
    const uint32_t smb = smem_u32(sm);

    for (int idx = tid; idx < 16 * 64; idx += 256) {
        const int r  = idx >> 6;
        const int c4 = idx & 63;
        const float4 x = *(const float4*)(inputs + (size_t)(row0 + r) * DD + c4 * 4);
        __nv_bfloat16 h[4], l[4];
        split_bf16(x.x, h[0], l[0]); split_bf16(x.y, h[1], l[1]);
        split_bf16(x.z, h[2], l[2]); split_bf16(x.w, h[3], l[3]);
        *(uint2*)(sm + PA_H + r * APITCH + c4 * 4) = *(const uint2*)h;
        *(uint2*)(sm + PA_L + r * APITCH + c4 * 4) = *(const uint2*)l;
        *(uint2*)(g_vh + (size_t)(row0 + r) * DD + c4 * 4) = *(const uint2*)h;
        *(uint2*)(g_vl + (size_t)(row0 + r) * DD + c4 * 4) = *(const uint2*)l;
    }
    for (int idx = tid; idx < 256 * 8 * 2; idx += 256) {
        const int plane = idx >> 11;
        const int k  = (idx >> 3) & 255;
        const int n8 = (idx & 7) * 8;
        const __nv_bfloat16* src = plane ? g_wbl : g_wbh;
        const uint4 v = *(const uint4*)(src + k * 64 + n8);
        *(uint4*)(sm + (plane ? PB_L : PB_H) + k * PITCH + n8) = v;
    }
    __syncthreads();

    float acc[4] = {0.f, 0.f, 0.f, 0.f};
    #pragma unroll
    for (int kk = 0; kk < 256; kk += 16) {
        uint32_t ah[4], al[4], bhf[2], blf[2];
        {
            const int r = lane & 15;
            const int c = kk + (lane >> 4) * 8;
            ldsm4(ah, smb + (uint32_t)(PA_H + r * APITCH + c) * 2);
            ldsm4(al, smb + (uint32_t)(PA_L + r * APITCH + c) * 2);
        }
        {
            const int kr = kk + (lane & 15);
            const int c  = wid * 8;
            ldsm2t(bhf, smb + (uint32_t)(PB_H + kr * PITCH + c) * 2);
            ldsm2t(blf, smb + (uint32_t)(PB_L + kr * PITCH + c) * 2);
        }
        mma16816(acc, ah, bhf);
        mma16816(acc, ah, blf);
        mma16816(acc, al, bhf);
    }

    #pragma unroll
    for (int half = 0; half < 2; half++) {
        const int r = row0 + (lane >> 2) + half * 8;
        const int c = wid * 8 + (lane & 3) * 2;
        const float v0 = acc[half * 2 + 0];
        const float v1 = acc[half * 2 + 1];
        if (c < UU) {
            g_q[r * UU + c]     = v0;
            g_q[r * UU + c + 1] = v1;
        } else {
            g_t[r * UU + c - 32] = v0 + __ldg(bh + c - 32);
            g_t[r * UU + c - 31] = v1 + __ldg(bh + c - 31);
        }
    }
}

// ===========================================================================
// Kernel B: alpha in REGISTERS (32/lane), softmax via shfl, store P hi/lo.
// ===========================================================================
__global__ __launch_bounds__(256) void alpha_kernel(
    const float* __restrict__ Wa, const float* __restrict__ ba)
{
    __shared__ float s_t[KC][UU + 4];
    __shared__ float s_q[QPB][UU];
    __shared__ float s_wa[UU];

    const int b    = blockIdx.x / (LL / QPB);
    const int q0   = (blockIdx.x % (LL / QPB)) * QPB;
    const int tid  = threadIdx.x;
    const int warp = tid >> 5;
    const int lane = tid & 31;

    s_q[warp][lane] = g_q[((size_t)b * LL + q0 + warp) * UU + lane];
    if (tid < UU) s_wa[tid] = Wa[tid];
    const float bav = ba[0];
    __syncthreads();

    float areg[32];
    const float4* q4  = (const float4*)&s_q[warp][0];
    const float4* wa4 = (const float4*)&s_wa[0];

    #pragma unroll
    for (int c = 0; c < LL / KC; c++) {
        const float4* gt4 = (const float4*)(g_t + ((size_t)b * LL + c * KC) * UU);
        for (int i = tid; i < KC * 8; i += 256)
            ((float4*)&s_t[i >> 3][0])[i & 7] = gt4[i];
        __syncthreads();
        #pragma unroll
        for (int j = 0; j < KC / 32; j++) {
            const int kl = j * 32 + lane;
            const float4* t4 = (const float4*)&s_t[kl][0];
            float a0 = 0.f, a1 = 0.f, a2 = 0.f, a3 = 0.f;
            #pragma unroll
            for (int u4 = 0; u4 < 8; u4++) {
                const float4 qv = q4[u4];
                const float4 tv = t4[u4];
                const float4 wv = wa4[u4];
                a0 = fmaf(htanh(qv.x + tv.x), wv.x, a0);
                a1 = fmaf(htanh(qv.y + tv.y), wv.y, a1);
                a2 = fmaf(htanh(qv.z + tv.z), wv.z, a2);
                a3 = fmaf(htanh(qv.w + tv.w), wv.w, a3);
            }
            areg[c * 2 + j] = bav + ((a0 + a1) + (a2 + a3));
        }
        __syncthreads();
    }

    float lmax = areg[0];
    #pragma unroll
    for (int i = 1; i < 32; i++) lmax = fmaxf(lmax, areg[i]);
    #pragma unroll
    for (int off = 16; off; off >>= 1)
        lmax = fmaxf(lmax, __shfl_xor_sync(0xffffffffu, lmax, off));

    float lsum = 0.0f;
    #pragma unroll
    for (int i = 0; i < 32; i++) {
        areg[i] = __expf(areg[i] - lmax);
        lsum += areg[i];
    }
    #pragma unroll
    for (int off = 16; off; off >>= 1)
        lsum += __shfl_xor_sync(0xffffffffu, lsum, off);
    const float inv = 1.0f / lsum;

    const size_t rowb = ((size_t)b * LL + q0 + warp) * LL;
    #pragma unroll
    for (int i = 0; i < 32; i++) {
        const float p = areg[i] * inv;
        const __nv_bfloat16 hi = __float2bfloat16(p);
        const __nv_bfloat16 lo = __float2bfloat16(p - __bfloat162float(hi));
        g_ph[rowb + i * 32 + lane] = hi;
        g_pl[rowb + i * 32 + lane] = lo;
    }
}

// ===========================================================================
// Kernel C: warp-MMA GEMM  C[32 q x 64 d] = P @ V (split bf16, fp32 acc).
// 3-stage cp.async pipeline; THREE independent accumulators (hh/hl/lh terms)
// to break the serial HMMA chain (6 independent chains per warp).
// ===========================================================================
#define S_AH 0
#define S_AL (32*PITCH)
#define S_BH (2*32*PITCH)
#define S_BL (S_BH + 64*PITCH)
#define STAGE_ELE (S_BL + 64*PITCH)          // 13824 bf16 per stage
#define NSTAGE 3
#define PV_SMEM_BYTES (NSTAGE*STAGE_ELE*2)   // 82944 B

__global__ __launch_bounds__(256) void pv_kernel(float* __restrict__ out)
{
    extern __shared__ __align__(16) __nv_bfloat16 sm[];
    const int tid    = threadIdx.x;
    const int wid    = tid >> 5;
    const int lane   = tid & 31;
    const int warp_m = wid >> 2;       // 0..1 (16 rows each)
    const int warp_n = wid & 3;        // 0..3 (16 cols each)
    const int q0g    = blockIdx.x * 32;
    const int b      = q0g >> 10;
    const int n0     = blockIdx.y * 64;
    const uint32_t smb = smem_u32(sm);

    int s_kind[6];
    const __nv_bfloat16* s_src[6];
    int s_r[6], s_o8[6];
    uint32_t s_soff[6];
    #pragma unroll
    for (int it = 0; it < 6; it++) {
        const int i = tid + it * 256;
        if (i < 512) {
            const int plane = i >> 8;
            s_kind[it] = 0;
            s_src[it]  = plane ? g_pl : g_ph;
            s_r[it]    = (i >> 3) & 31;
            s_o8[it]   = (i & 7) * 8;
            s_soff[it] = (plane ? S_AL : S_AH) + s_r[it] * PITCH + s_o8[it];
        } else {
            const int j = i - 512;
            const int plane = j >> 9;
            s_kind[it] = 1;
            s_src[it]  = plane ? g_vl : g_vh;
            s_r[it]    = (j >> 3) & 63;
            s_o8[it]   = (j & 7) * 8;
            s_soff[it] = (plane ? S_BL : S_BH) + s_r[it] * PITCH + s_o8[it];
        }
    }

    auto issue_stage = [&](int kc0, int st) {
        const uint32_t sb = smb + (uint32_t)(st * STAGE_ELE) * 2;
        #pragma unroll
        for (int it = 0; it < 6; it++) {
            const void* g = (s_kind[it] == 0)
                ? (const void*)(s_src[it] + (size_t)(q0g + s_r[it]) * LL + kc0 + s_o8[it])
                : (const void*)(s_src[it] + (size_t)(b * LL + kc0 + s_r[it]) * DD + n0 + s_o8[it]);
            cpasync16(sb + s_soff[it] * 2, g);
        }
        cpasync_commit();
    };

    // 3 independent accumulators per nt: hh, hl, lh
    float acc_hh[2][4], acc_hl[2][4], acc_lh[2][4];
    #pragma unroll
    for (int nt = 0; nt < 2; nt++)
        #pragma unroll
        for (int j = 0; j < 4; j++) {
            acc_hh[nt][j] = 0.f; acc_hl[nt][j] = 0.f; acc_lh[nt][j] = 0.f;
        }

    issue_stage(0, 0);
    issue_stage(KCH, 1);

    #pragma unroll 1
    for (int c = 0; c < LL / KCH; c++) {
        if (c < LL / KCH - 1) cpasync_wait1(); else cpasync_wait0();
        __syncthreads();

        if (c + 2 < LL / KCH)
            issue_stage((c + 2) * KCH, (c + 2) % NSTAGE);

        const uint32_t st = smb + (uint32_t)((c % NSTAGE) * STAGE_ELE) * 2;
        #pragma unroll
        for (int kk = 0; kk < KCH; kk += 16) {
            uint32_t ah[4], al[4], bh[2][2], bl[2][2];
            {
                const int r = warp_m * 16 + (lane & 15);
                const int col = kk + (lane >> 4) * 8;
                ldsm4(ah, st + (uint32_t)(S_AH + r * PITCH + col) * 2);
                ldsm4(al, st + (uint32_t)(S_AL + r * PITCH + col) * 2);
            }
            #pragma unroll
            for (int nt = 0; nt < 2; nt++) {
                const int kr  = kk + (lane & 15);
                const int col = warp_n * 16 + nt * 8;
                ldsm2t(bh[nt], st + (uint32_t)(S_BH + kr * PITCH + col) * 2);
                ldsm2t(bl[nt], st + (uint32_t)(S_BL + kr * PITCH + col) * 2);
            }
            #pragma unroll
            for (int nt = 0; nt < 2; nt++) {
                mma16816(acc_hh[nt], ah, bh[nt]);   // independent chain 1
                mma16816(acc_hl[nt], ah, bl[nt]);   // independent chain 2
                mma16816(acc_lh[nt], al, bh[nt]);   // independent chain 3
            }
        }
    }

    #pragma unroll
    for (int nt = 0; nt < 2; nt++) {
        const int row = q0g + warp_m * 16 + (lane >> 2);
        const int col = n0 + warp_n * 16 + nt * 8 + (lane & 3) * 2;
        float* o = out + (size_t)row * DD + col;
        o[0] = acc_hh[nt][0] + (acc_hl[nt][0] + acc_lh[nt][0]);
        o[1] = acc_hh[nt][1] + (acc_hl[nt][1] + acc_lh[nt][1]);
        o[8 * DD + 0] = acc_hh[nt][2] + (acc_hl[nt][2] + acc_lh[nt][2]);
        o[8 * DD + 1] = acc_hh[nt][3] + (acc_hl[nt][3] + acc_lh[nt][3]);
    }
}

// ===========================================================================
extern "C" void kernel_launch(void* const* d_in, const int* in_sizes, int n_in,
                              void* d_out, int out_size) {
    const float* inputs = (const float*)d_in[0];
    const float* Wt     = (const float*)d_in[1];
    const float* Wx     = (const float*)d_in[2];
    const float* bh     = (const float*)d_in[3];
    const float* Wa     = (const float*)d_in[4];
    const float* ba     = (const float*)d_in[5];
    float* out = (float*)d_out;

    cudaFuncSetAttribute(proj_mma_kernel, cudaFuncAttributeMaxDynamicSharedMemorySize, PROJ_SMEM);
    cudaFuncSetAttribute(pv_kernel, cudaFuncAttributeMaxDynamicSharedMemorySize, PV_SMEM_BYTES);
    cudaFuncSetAttribute(pv_kernel, cudaFuncAttributePreferredSharedMemoryCarveout, 100);

    wsplit_kernel<<<16, 256>>>(Wt, Wx);
    proj_mma_kernel<<<BB * LL / 16, 256, PROJ_SMEM>>>(inputs, bh);
    alpha_kernel<<<BB * LL / QPB, 256>>>(Wa, ba);
    pv_kernel<<<dim3(BB * LL / 32, DD / 64), 256, PV_SMEM_BYTES>>>(out);
}

// round 15
// speedup vs baseline: 1.0756x; 1.0361x over previous
#include <cuda_runtime.h>
#include <cuda_fp16.h>
#include <cstdint>

#define BB  2
#define LL  1024
#define DD  256
#define UU  32
#define QPB 8
#define KC  64
#define KCH 64       // k-chunk for pv gemm
#define PITCH 72     // smem row pitch in fp16 (144B: conflict-free ldmatrix)

// ---- device scratch (no allocs allowed) ----
__device__ __align__(16) float g_q[BB*LL*UU];
__device__ __align__(16) float g_t[BB*LL*UU];
__device__ __align__(16) __half g_ph[BB*LL*LL];   // P fp16 (normalized), single plane
__device__ __align__(16) __half g_vh[BB*LL*DD];   // V hi  [b][k][d] fp16
__device__ __align__(16) __half g_vl[BB*LL*DD];   // V lo  fp16
__device__ __align__(16) __half g_wbh[DD*64];     // W stacked [k][n] hi fp16
__device__ __align__(16) __half g_wbl[DD*64];     // W stacked lo fp16

__device__ __forceinline__ float htanh(float x) {
    float y; asm("tanh.approx.f32 %0, %1;" : "=f"(y) : "f"(x)); return y;
}
__device__ __forceinline__ uint32_t smem_u32(const void* p) {
    uint32_t a;
    asm("{ .reg .u64 t; cvta.to.shared.u64 t, %1; cvt.u32.u64 %0, t; }" : "=r"(a) : "l"(p));
    return a;
}
__device__ __forceinline__ void ldsm4(uint32_t* r, uint32_t addr) {
    asm volatile("ldmatrix.sync.aligned.m8n8.x4.shared.b16 {%0,%1,%2,%3}, [%4];"
        : "=r"(r[0]), "=r"(r[1]), "=r"(r[2]), "=r"(r[3]) : "r"(addr));
}
__device__ __forceinline__ void ldsm2t(uint32_t* r, uint32_t addr) {
    asm volatile("ldmatrix.sync.aligned.m8n8.x2.trans.shared.b16 {%0,%1}, [%2];"
        : "=r"(r[0]), "=r"(r[1]) : "r"(addr));
}
// fp16 inputs, fp32 accumulate
__device__ __forceinline__ void mma16816(float* c, const uint32_t* a, const uint32_t* b) {
    asm volatile("mma.sync.aligned.m16n8k16.row.col.f32.f16.f16.f32 "
        "{%0,%1,%2,%3}, {%4,%5,%6,%7}, {%8,%9}, {%0,%1,%2,%3};"
        : "+f"(c[0]), "+f"(c[1]), "+f"(c[2]), "+f"(c[3])
        : "r"(a[0]), "r"(a[1]), "r"(a[2]), "r"(a[3]), "r"(b[0]), "r"(b[1]));
}
__device__ __forceinline__ void split_f16(float v, __half& h, __half& l) {
    h = __float2half_rn(v);
    l = __float2half_rn(v - __half2float(h));
}
__device__ __forceinline__ void cpasync16(uint32_t saddr, const void* gptr) {
    asm volatile("cp.async.cg.shared.global [%0], [%1], 16;" :: "r"(saddr), "l"(gptr));
}
__device__ __forceinline__ void cpasync_commit() {
    asm volatile("cp.async.commit_group;");
}
__device__ __forceinline__ void cpasync_wait0() {
    asm volatile("cp.async.wait_group 0;");
}
__device__ __forceinline__ void cpasync_wait1() {
    asm volatile("cp.async.wait_group 1;");
}

// ===========================================================================
// Kernel W: one-time split of [Wt | Wx^T] into fp16 hi/lo, [k][64] layout.
// ===========================================================================
__global__ __launch_bounds__(256) void wsplit_kernel(
    const float* __restrict__ Wt, const float* __restrict__ Wx)
{
    const int base = blockIdx.x * 1024;
    for (int i = 0; i < 4; i++) {
        const int idx = base + i * 256 + threadIdx.x;
        const int k = idx >> 6, n = idx & 63;
        const float v = (n < UU) ? Wt[k * UU + n] : Wx[(n - UU) * DD + k];
        __half h, l;
        split_f16(v, h, l);
        g_wbh[idx] = h;
        g_wbl[idx] = l;
    }
}

// ===========================================================================
// Kernel A (MMA): [q | t] = X @ [Wt | Wx^T], split-fp16 (3 terms), M-tile 16.
// Also writes X hi/lo fp16 to g_vh/g_vl (V operand for pv).
// ===========================================================================
#define APITCH 264
#define PA_H 0
#define PA_L (16*APITCH)
#define PB_H (2*16*APITCH)
#define PB_L (PB_H + 256*PITCH)
#define PROJ_SMEM ((PB_L + 256*PITCH) * 2)

__global__ __launch_bounds__(256) void proj_mma_kernel(
    const float* __restrict__ inputs, const float* __restrict__ bh)
{
    extern __shared__ __align__(16) __half sm[];
    const int tid  = threadIdx.x;
    const int wid  = tid >> 5;
    const int lane = tid & 31;
    const int row0 = blockIdx.x * 16;
    const uint32_t smb = smem_u32(sm);

    for (int idx = tid; idx < 16 * 64; idx += 256) {
        const int r  = idx >> 6;
        const int c4 = idx & 63;
        const float4 x = *(const float4*)(inputs + (size_t)(row0 + r) * DD + c4 * 4);
        __half h[4], l[4];
        split_f16(x.x, h[0], l[0]); split_f16(x.y, h[1], l[1]);
        split_f16(x.z, h[2], l[2]); split_f16(x.w, h[3], l[3]);
        *(uint2*)(sm + PA_H + r * APITCH + c4 * 4) = *(const uint2*)h;
        *(uint2*)(sm + PA_L + r * APITCH + c4 * 4) = *(const uint2*)l;
        *(uint2*)(g_vh + (size_t)(row0 + r) * DD + c4 * 4) = *(const uint2*)h;
        *(uint2*)(g_vl + (size_t)(row0 + r) * DD + c4 * 4) = *(const uint2*)l;
    }
    for (int idx = tid; idx < 256 * 8 * 2; idx += 256) {
        const int plane = idx >> 11;
        const int k  = (idx >> 3) & 255;
        const int n8 = (idx & 7) * 8;
        const __half* src = plane ? g_wbl : g_wbh;
        const uint4 v = *(const uint4*)(src + k * 64 + n8);
        *(uint4*)(sm + (plane ? PB_L : PB_H) + k * PITCH + n8) = v;
    }
    __syncthreads();

    float acc[4] = {0.f, 0.f, 0.f, 0.f};
    #pragma unroll
    for (int kk = 0; kk < 256; kk += 16) {
        uint32_t ah[4], al[4], bhf[2], blf[2];
        {
            const int r = lane & 15;
            const int c = kk + (lane >> 4) * 8;
            ldsm4(ah, smb + (uint32_t)(PA_H + r * APITCH + c) * 2);
            ldsm4(al, smb + (uint32_t)(PA_L + r * APITCH + c) * 2);
        }
        {
            const int kr = kk + (lane & 15);
            const int c  = wid * 8;
            ldsm2t(bhf, smb + (uint32_t)(PB_H + kr * PITCH + c) * 2);
            ldsm2t(blf, smb + (uint32_t)(PB_L + kr * PITCH + c) * 2);
        }
        mma16816(acc, ah, bhf);
        mma16816(acc, ah, blf);
        mma16816(acc, al, bhf);
    }

    #pragma unroll
    for (int half = 0; half < 2; half++) {
        const int r = row0 + (lane >> 2) + half * 8;
        const int c = wid * 8 + (lane & 3) * 2;
        const float v0 = acc[half * 2 + 0];
        const float v1 = acc[half * 2 + 1];
        if (c < UU) {
            g_q[r * UU + c]     = v0;
            g_q[r * UU + c + 1] = v1;
        } else {
            g_t[r * UU + c - 32] = v0 + __ldg(bh + c - 32);
            g_t[r * UU + c - 31] = v1 + __ldg(bh + c - 31);
        }
    }
}

// ===========================================================================
// Kernel B: alpha in REGISTERS (32/lane), softmax via shfl, store P fp16.
// ===========================================================================
__global__ __launch_bounds__(256) void alpha_kernel(
    const float* __restrict__ Wa, const float* __restrict__ ba)
{
    __shared__ float s_t[KC][UU + 4];
    __shared__ float s_q[QPB][UU];
    __shared__ float s_wa[UU];

    const int b    = blockIdx.x / (LL / QPB);
    const int q0   = (blockIdx.x % (LL / QPB)) * QPB;
    const int tid  = threadIdx.x;
    const int warp = tid >> 5;
    const int lane = tid & 31;

    s_q[warp][lane] = g_q[((size_t)b * LL + q0 + warp) * UU + lane];
    if (tid < UU) s_wa[tid] = Wa[tid];
    const float bav = ba[0];
    __syncthreads();

    float areg[32];
    const float4* q4  = (const float4*)&s_q[warp][0];
    const float4* wa4 = (const float4*)&s_wa[0];

    #pragma unroll
    for (int c = 0; c < LL / KC; c++) {
        const float4* gt4 = (const float4*)(g_t + ((size_t)b * LL + c * KC) * UU);
        for (int i = tid; i < KC * 8; i += 256)
            ((float4*)&s_t[i >> 3][0])[i & 7] = gt4[i];
        __syncthreads();
        #pragma unroll
        for (int j = 0; j < KC / 32; j++) {
            const int kl = j * 32 + lane;
            const float4* t4 = (const float4*)&s_t[kl][0];
            float a0 = 0.f, a1 = 0.f, a2 = 0.f, a3 = 0.f;
            #pragma unroll
            for (int u4 = 0; u4 < 8; u4++) {
                const float4 qv = q4[u4];
                const float4 tv = t4[u4];
                const float4 wv = wa4[u4];
                a0 = fmaf(htanh(qv.x + tv.x), wv.x, a0);
                a1 = fmaf(htanh(qv.y + tv.y), wv.y, a1);
                a2 = fmaf(htanh(qv.z + tv.z), wv.z, a2);
                a3 = fmaf(htanh(qv.w + tv.w), wv.w, a3);
            }
            areg[c * 2 + j] = bav + ((a0 + a1) + (a2 + a3));
        }
        __syncthreads();
    }

    float lmax = areg[0];
    #pragma unroll
    for (int i = 1; i < 32; i++) lmax = fmaxf(lmax, areg[i]);
    #pragma unroll
    for (int off = 16; off; off >>= 1)
        lmax = fmaxf(lmax, __shfl_xor_sync(0xffffffffu, lmax, off));

    float lsum = 0.0f;
    #pragma unroll
    for (int i = 0; i < 32; i++) {
        areg[i] = __expf(areg[i] - lmax);
        lsum += areg[i];
    }
    #pragma unroll
    for (int off = 16; off; off >>= 1)
        lsum += __shfl_xor_sync(0xffffffffu, lsum, off);
    const float inv = 1.0f / lsum;

    const size_t rowb = ((size_t)b * LL + q0 + warp) * LL;
    #pragma unroll
    for (int i = 0; i < 32; i++) {
        g_ph[rowb + i * 32 + lane] = __float2half_rn(areg[i] * inv);
    }
}

// ===========================================================================
// Kernel C: warp-MMA GEMM  C[32 q x 64 d] = P @ V, split-fp16 TWO terms:
// Ph@Vh + Ph@Vl (Pl dropped: rel err ~2e-4 << 1e-3). 3-stage cp.async.
// Stage layout (fp16 units): [A 32xP][BH 64xP][BL 64xP]
// ===========================================================================
#define S_A  0
#define S_BH (32*PITCH)
#define S_BL (S_BH + 64*PITCH)
#define STAGE_ELE (S_BL + 64*PITCH)          // 11520 fp16 per stage
#define NSTAGE 3
#define PV_SMEM_BYTES (NSTAGE*STAGE_ELE*2)   // 69120 B

__global__ __launch_bounds__(256) void pv_kernel(float* __restrict__ out)
{
    extern __shared__ __align__(16) __half sm[];
    const int tid    = threadIdx.x;
    const int wid    = tid >> 5;
    const int lane   = tid & 31;
    const int warp_m = wid >> 2;       // 0..1 (16 rows each)
    const int warp_n = wid & 3;        // 0..3 (16 cols each)
    const int q0g    = blockIdx.x * 32;
    const int b      = q0g >> 10;
    const int n0     = blockIdx.y * 64;
    const uint32_t smb = smem_u32(sm);

    // per-thread staging slots: 5 x 16B per stage (A: 256 vecs, B: 1024 vecs)
    int s_kind[5];
    const __half* s_src[5];
    int s_r[5], s_o8[5];
    uint32_t s_soff[5];
    #pragma unroll
    for (int it = 0; it < 5; it++) {
        const int i = tid + it * 256;        // 0..1279
        if (i < 256) {
            s_kind[it] = 0;
            s_src[it]  = g_ph;
            s_r[it]    = i >> 3;
            s_o8[it]   = (i & 7) * 8;
            s_soff[it] = S_A + s_r[it] * PITCH + s_o8[it];
        } else {
            const int j = i - 256;           // 0..1023
            const int plane = j >> 9;
            s_kind[it] = 1;
            s_src[it]  = plane ? g_vl : g_vh;
            s_r[it]    = (j >> 3) & 63;
            s_o8[it]   = (j & 7) * 8;
            s_soff[it] = (plane ? S_BL : S_BH) + s_r[it] * PITCH + s_o8[it];
        }
    }

    auto issue_stage = [&](int kc0, int st) {
        const uint32_t sb = smb + (uint32_t)(st * STAGE_ELE) * 2;
        #pragma unroll
        for (int it = 0; it < 5; it++) {
            const void* g = (s_kind[it] == 0)
                ? (const void*)(s_src[it] + (size_t)(q0g + s_r[it]) * LL + kc0 + s_o8[it])
                : (const void*)(s_src[it] + (size_t)(b * LL + kc0 + s_r[it]) * DD + n0 + s_o8[it]);
            cpasync16(sb + s_soff[it] * 2, g);
        }
        cpasync_commit();
    };

    float acc_hh[2][4], acc_hl[2][4];
    #pragma unroll
    for (int nt = 0; nt < 2; nt++)
        #pragma unroll
        for (int j = 0; j < 4; j++) {
            acc_hh[nt][j] = 0.f; acc_hl[nt][j] = 0.f;
        }

    issue_stage(0, 0);
    issue_stage(KCH, 1);

    #pragma unroll 1
    for (int c = 0; c < LL / KCH; c++) {
        if (c < LL / KCH - 1) cpasync_wait1(); else cpasync_wait0();
        __syncthreads();

        if (c + 2 < LL / KCH)
            issue_stage((c + 2) * KCH, (c + 2) % NSTAGE);

        const uint32_t st = smb + (uint32_t)((c % NSTAGE) * STAGE_ELE) * 2;
        #pragma unroll
        for (int kk = 0; kk < KCH; kk += 16) {
            uint32_t a[4], bh[2][2], bl[2][2];
            {
                const int r = warp_m * 16 + (lane & 15);
                const int col = kk + (lane >> 4) * 8;
                ldsm4(a, st + (uint32_t)(S_A + r * PITCH + col) * 2);
            }
            #pragma unroll
            for (int nt = 0; nt < 2; nt++) {
                const int kr  = kk + (lane & 15);
                const int col = warp_n * 16 + nt * 8;
                ldsm2t(bh[nt], st + (uint32_t)(S_BH + kr * PITCH + col) * 2);
                ldsm2t(bl[nt], st + (uint32_t)(S_BL + kr * PITCH + col) * 2);
            }
            #pragma unroll
            for (int nt = 0; nt < 2; nt++) {
                mma16816(acc_hh[nt], a, bh[nt]);   // independent chain 1
                mma16816(acc_hl[nt], a, bl[nt]);   // independent chain 2
            }
        }
    }

    #pragma unroll
    for (int nt = 0; nt < 2; nt++) {
        const int row = q0g + warp_m * 16 + (lane >> 2);
        const int col = n0 + warp_n * 16 + nt * 8 + (lane & 3) * 2;
        float* o = out + (size_t)row * DD + col;
        o[0] = acc_hh[nt][0] + acc_hl[nt][0];
        o[1] = acc_hh[nt][1] + acc_hl[nt][1];
        o[8 * DD + 0] = acc_hh[nt][2] + acc_hl[nt][2];
        o[8 * DD + 1] = acc_hh[nt][3] + acc_hl[nt][3];
    }
}

// ===========================================================================
extern "C" void kernel_launch(void* const* d_in, const int* in_sizes, int n_in,
                              void* d_out, int out_size) {
    const float* inputs = (const float*)d_in[0];
    const float* Wt     = (const float*)d_in[1];
    const float* Wx     = (const float*)d_in[2];
    const float* bh     = (const float*)d_in[3];
    const float* Wa     = (const float*)d_in[4];
    const float* ba     = (const float*)d_in[5];
    float* out = (float*)d_out;

    cudaFuncSetAttribute(proj_mma_kernel, cudaFuncAttributeMaxDynamicSharedMemorySize, PROJ_SMEM);
    cudaFuncSetAttribute(pv_kernel, cudaFuncAttributeMaxDynamicSharedMemorySize, PV_SMEM_BYTES);
    cudaFuncSetAttribute(pv_kernel, cudaFuncAttributePreferredSharedMemoryCarveout, 100);

    wsplit_kernel<<<16, 256>>>(Wt, Wx);
    proj_mma_kernel<<<BB * LL / 16, 256, PROJ_SMEM>>>(inputs, bh);
    alpha_kernel<<<BB * LL / QPB, 256>>>(Wa, ba);
    pv_kernel<<<dim3(BB * LL / 32, DD / 64), 256, PV_SMEM_BYTES>>>(out);
}